// round 8
// baseline (speedup 1.0000x reference)
#include <cuda_runtime.h>
#include <cuda_fp16.h>

#define USER_NUM 50000
#define N_NODES  100000
#define EMB      64
#define ADJ_NNZ  1600000
#define S_NNZ    800000
#define TOT      (N_NODES * EMB)
#define ADJ_CAP  96     // Poisson(16) tail: P(deg>96) ~ 1e-40 per row
#define S_CAP    64     // Poisson(16)

// ---------------- scratch (device globals; zero-initialized at load) ----------------
__device__ __half g_egoA[TOT];              // ego0 (fp16 copy of inputs)
__device__ __half g_egoB[TOT];              // ego1
__device__ __half g_egoC[TOT];              // ego2
__device__ __half g_h[USER_NUM * EMB];

__device__ int   g_adj_cnt[N_NODES];        // invariant: zero at kernel_launch entry
__device__ uint2 g_adj_b[(size_t)N_NODES * ADJ_CAP];
__device__ int   g_s_cnt[USER_NUM];         // invariant: zero at kernel_launch entry
__device__ uint2 g_s_b[(size_t)USER_NUM * S_CAP];

// ---------------- single-pass build: bucket-scatter both edge lists + init ego0 ----------------
__global__ void build_kernel(const int* __restrict__ adj_rows, const int* __restrict__ adj_cols,
                             const float* __restrict__ adj_vals, int* __restrict__ adj_cnt,
                             uint2* __restrict__ adj_b,
                             const int* __restrict__ s_rows, const int* __restrict__ s_cols,
                             const float* __restrict__ s_vals, int* __restrict__ s_cnt,
                             uint2* __restrict__ s_b,
                             const float* __restrict__ ue, const float* __restrict__ ie,
                             __half* __restrict__ ego) {
    int i = blockIdx.x * blockDim.x + threadIdx.x;
    if (i < ADJ_NNZ) {
        int r = __ldcs(adj_rows + i);
        int p = atomicAdd(adj_cnt + r, 1);
        if (p < ADJ_CAP)
            adj_b[(size_t)r * ADJ_CAP + p] =
                make_uint2((unsigned)__ldcs(adj_cols + i), __float_as_uint(__ldcs(adj_vals + i)));
    } else if (i < ADJ_NNZ + S_NNZ) {
        int j = i - ADJ_NNZ;
        int r = __ldcs(s_rows + j);
        int p = atomicAdd(s_cnt + r, 1);
        if (p < S_CAP)
            s_b[(size_t)r * S_CAP + p] =
                make_uint2((unsigned)__ldcs(s_cols + j), __float_as_uint(__ldcs(s_vals + j)));
    } else if (i < ADJ_NNZ + S_NNZ + TOT / 2) {
        int j = i - (ADJ_NNZ + S_NNZ);             // half2/float2 index
        const float2* src = (j < USER_NUM * EMB / 2) ? (const float2*)ue
                                                     : (const float2*)ie - USER_NUM * EMB / 2;
        float2 v = src[j];
        ((__half2*)ego)[j] = __floats2half2_rn(v.x, v.y);
    }
}

// ---------------- warp-per-row gather core (direct cv loads, MLP-4) ----------------
template <bool DUAL>
__device__ __forceinline__ float2 row_accum(const uint2* __restrict__ cv, int e, int end,
                                            int lane, const __half* __restrict__ ego,
                                            const __half* __restrict__ h, float2 a) {
    for (; e + 3 < end; e += 4) {
        uint2 cv0 = __ldg(cv + e),     cv1 = __ldg(cv + e + 1);
        uint2 cv2 = __ldg(cv + e + 2), cv3 = __ldg(cv + e + 3);
        const __half* b0 = (DUAL && cv0.x < USER_NUM) ? h : ego;
        const __half* b1 = (DUAL && cv1.x < USER_NUM) ? h : ego;
        const __half* b2 = (DUAL && cv2.x < USER_NUM) ? h : ego;
        const __half* b3 = (DUAL && cv3.x < USER_NUM) ? h : ego;
        float2 x0 = __half22float2(__ldg((const __half2*)(b0 + (size_t)cv0.x * EMB) + lane));
        float2 x1 = __half22float2(__ldg((const __half2*)(b1 + (size_t)cv1.x * EMB) + lane));
        float2 x2 = __half22float2(__ldg((const __half2*)(b2 + (size_t)cv2.x * EMB) + lane));
        float2 x3 = __half22float2(__ldg((const __half2*)(b3 + (size_t)cv3.x * EMB) + lane));
        float w0 = __uint_as_float(cv0.y), w1 = __uint_as_float(cv1.y);
        float w2 = __uint_as_float(cv2.y), w3 = __uint_as_float(cv3.y);
        a.x = fmaf(w0, x0.x, fmaf(w1, x1.x, fmaf(w2, x2.x, fmaf(w3, x3.x, a.x))));
        a.y = fmaf(w0, x0.y, fmaf(w1, x1.y, fmaf(w2, x2.y, fmaf(w3, x3.y, a.y))));
    }
    for (; e < end; e++) {
        uint2 cv0 = __ldg(cv + e);
        float w0 = __uint_as_float(cv0.y);
        const __half* b0 = (DUAL && cv0.x < USER_NUM) ? h : ego;
        float2 x0 = __half22float2(__ldg((const __half2*)(b0 + (size_t)cv0.x * EMB) + lane));
        a.x = fmaf(w0, x0.x, a.x);
        a.y = fmaf(w0, x0.y, a.y);
    }
    return a;
}

// h[r] = ego[r] + sum val*ego[col]   (users). clear!=0: re-zero s_cnt[row] after reading.
__global__ void s_spmm_kernel(const int* __restrict__ cnt, const uint2* __restrict__ bkt,
                              const __half* __restrict__ ego, __half* __restrict__ h,
                              int* __restrict__ cnt_w, int clear) {
    int row = blockIdx.x * (blockDim.x >> 5) + (threadIdx.x >> 5);
    int lane = threadIdx.x & 31;
    if (row >= USER_NUM) return;
    int deg = min(__ldg(cnt + row), S_CAP);
    if (clear && lane == 0) cnt_w[row] = 0;
    const uint2* cv = bkt + (size_t)row * S_CAP;
    float2 a = __half22float2(((const __half2*)(ego + (size_t)row * EMB))[lane]); // self term
    a = row_accum<false>(cv, 0, deg, lane, ego, ego, a);
    ((__half2*)(h + (size_t)row * EMB))[lane] = __floats2half2_rn(a.x, a.y);
}

// a = sum val*sel(col); sel = h (users) / ego (items)
// last==0: nxt[r] = half(a)
// last==1: out[r] = (input_row + ego1[r] + ego2[r] + a) * 0.25 ; re-zero adj_cnt[row]
__global__ void adj_spmm_kernel(const int* __restrict__ cnt, const uint2* __restrict__ bkt,
                                const __half* __restrict__ ego, const __half* __restrict__ h,
                                __half* __restrict__ nxt,
                                const float* __restrict__ ue, const float* __restrict__ ie,
                                const __half* __restrict__ ego1,
                                float* __restrict__ out, int* __restrict__ cnt_w, int last) {
    int row = blockIdx.x * (blockDim.x >> 5) + (threadIdx.x >> 5);
    int lane = threadIdx.x & 31;
    if (row >= N_NODES) return;
    int deg = min(__ldg(cnt + row), ADJ_CAP);
    if (last && lane == 0) cnt_w[row] = 0;
    const uint2* cv = bkt + (size_t)row * ADJ_CAP;
    float2 a = row_accum<true>(cv, 0, deg, lane, ego, h, make_float2(0.f, 0.f));
    if (last) {
        const float2* in0 = (row < USER_NUM)
            ? (const float2*)ue + (size_t)row * (EMB / 2)
            : (const float2*)ie + (size_t)(row - USER_NUM) * (EMB / 2);
        float2 v0 = __ldg(in0 + lane);                                            // ego0 (exact)
        float2 v1 = __half22float2(__ldg((const __half2*)(ego1 + (size_t)row * EMB) + lane));
        float2 v2 = __half22float2(__ldg((const __half2*)(ego  + (size_t)row * EMB) + lane));
        ((float2*)(out + (size_t)row * EMB))[lane] =
            make_float2((v0.x + v1.x + v2.x + a.x) * 0.25f,
                        (v0.y + v1.y + v2.y + a.y) * 0.25f);
    } else {
        ((__half2*)(nxt + (size_t)row * EMB))[lane] = __floats2half2_rn(a.x, a.y);
    }
}

extern "C" void kernel_launch(void* const* d_in, const int* in_sizes, int n_in,
                              void* d_out, int out_size) {
    const float* ue       = (const float*)d_in[0];
    const float* ie       = (const float*)d_in[1];
    const int*   adj_rows = (const int*)d_in[2];
    const int*   adj_cols = (const int*)d_in[3];
    const float* adj_vals = (const float*)d_in[4];
    const int*   s_rows   = (const int*)d_in[5];
    const int*   s_cols   = (const int*)d_in[6];
    const float* s_vals   = (const float*)d_in[7];

    __half *egoA, *egoB, *egoC, *h;
    int *adj_cnt, *s_cnt;
    uint2 *adj_b, *s_b;
    cudaGetSymbolAddress((void**)&egoA,    g_egoA);
    cudaGetSymbolAddress((void**)&egoB,    g_egoB);
    cudaGetSymbolAddress((void**)&egoC,    g_egoC);
    cudaGetSymbolAddress((void**)&h,       g_h);
    cudaGetSymbolAddress((void**)&adj_cnt, g_adj_cnt);
    cudaGetSymbolAddress((void**)&adj_b,   g_adj_b);
    cudaGetSymbolAddress((void**)&s_cnt,   g_s_cnt);
    cudaGetSymbolAddress((void**)&s_b,     g_s_b);

    const int TPB = 256;

    // ---- single-pass bucket build + ego0 init (1 kernel) ----
    {
        int tot = ADJ_NNZ + S_NNZ + TOT / 2;
        build_kernel<<<(tot + TPB - 1) / TPB, TPB>>>(adj_rows, adj_cols, adj_vals, adj_cnt, adj_b,
                                                     s_rows, s_cols, s_vals, s_cnt, s_b,
                                                     ue, ie, egoA);
    }

    // ---- 3 layers (6 kernels); ego0=egoA, ego1=egoB, ego2=egoC ----
    const int wpb = TPB / 32;
    const int s_blocks   = (USER_NUM + wpb - 1) / wpb;
    const int adj_blocks = (N_NODES + wpb - 1) / wpb;

    // layer 0: read egoA -> write egoB
    s_spmm_kernel<<<s_blocks, TPB>>>(s_cnt, s_b, egoA, h, s_cnt, 0);
    adj_spmm_kernel<<<adj_blocks, TPB>>>(adj_cnt, adj_b, egoA, h, egoB,
                                         ue, ie, egoB, (float*)d_out, adj_cnt, 0);
    // layer 1: read egoB -> write egoC
    s_spmm_kernel<<<s_blocks, TPB>>>(s_cnt, s_b, egoB, h, s_cnt, 0);
    adj_spmm_kernel<<<adj_blocks, TPB>>>(adj_cnt, adj_b, egoB, h, egoC,
                                         ue, ie, egoB, (float*)d_out, adj_cnt, 0);
    // layer 2: read egoC -> fused final: out = (input + egoB + egoC + a) / 4 ; clears cnts
    s_spmm_kernel<<<s_blocks, TPB>>>(s_cnt, s_b, egoC, h, s_cnt, 1);
    adj_spmm_kernel<<<adj_blocks, TPB>>>(adj_cnt, adj_b, egoC, h, /*nxt*/egoA,
                                         ue, ie, egoB, (float*)d_out, adj_cnt, 1);
}

// round 9
// speedup vs baseline: 1.5782x; 1.5782x over previous
#include <cuda_runtime.h>
#include <cuda_fp16.h>

#define USER_NUM 50000
#define N_NODES  100000
#define EMB      64
#define ADJ_NNZ  1600000
#define S_NNZ    800000
#define TOT      (N_NODES * EMB)
#define SB 512
#define ADJ_NB ((N_NODES + SB - 1) / SB)    // 196
#define S_NB   ((USER_NUM + SB - 1) / SB)   // 98

// ---------------- scratch (device globals; zero-initialized at load) ----------------
__device__ __half g_egoA[TOT];              // ego0 (fp16 copy of inputs)
__device__ __half g_egoB[TOT];              // ego1
__device__ __half g_egoC[TOT];              // ego2
__device__ __half g_h[USER_NUM * EMB];

__device__ int   g_adj_cnt[N_NODES];        // invariant: zero at kernel_launch entry
__device__ int   g_adj_ptr[N_NODES + 1];
__device__ int   g_adj_w[N_NODES];
__device__ uint2 g_adj_cv[ADJ_NNZ];

__device__ int   g_s_cnt[USER_NUM];         // invariant: zero at kernel_launch entry
__device__ int   g_s_ptr[USER_NUM + 1];
__device__ int   g_s_w[USER_NUM];
__device__ uint2 g_s_cv[S_NNZ];

__device__ int   g_bsumsA[SB];
__device__ int   g_bsumsB[SB];

// ---------------- fused: hist(adj) + hist(s) + init(ego0 fp16) ----------------
__global__ void hist_init_kernel(const int* __restrict__ adj_rows, const int* __restrict__ s_rows,
                                 int* __restrict__ adj_cnt, int* __restrict__ s_cnt,
                                 const float* __restrict__ ue, const float* __restrict__ ie,
                                 __half* __restrict__ ego) {
    int i = blockIdx.x * blockDim.x + threadIdx.x;
    if (i < ADJ_NNZ) {
        atomicAdd(adj_cnt + __ldcs(adj_rows + i), 1);
    } else if (i < ADJ_NNZ + S_NNZ) {
        atomicAdd(s_cnt + __ldcs(s_rows + (i - ADJ_NNZ)), 1);
    } else if (i < ADJ_NNZ + S_NNZ + TOT / 2) {
        int j = i - (ADJ_NNZ + S_NNZ);             // half2/float2 index
        const float2* src = (j < USER_NUM * EMB / 2) ? (const float2*)ue
                                                     : (const float2*)ie - USER_NUM * EMB / 2;
        float2 v = src[j];
        ((__half2*)ego)[j] = __floats2half2_rn(v.x, v.y);
    }
}

// per-block exclusive scans of both count arrays
__global__ void scan1_kernel(const int* __restrict__ adj_cnt, int* __restrict__ adj_ptr,
                             const int* __restrict__ s_cnt, int* __restrict__ s_ptr,
                             int* __restrict__ bsumsA, int* __restrict__ bsumsB) {
    __shared__ int sh[SB];
    const int* cnt; int* ptr; int* bsums; int n; int b;
    if (blockIdx.x < ADJ_NB) { cnt = adj_cnt; ptr = adj_ptr; bsums = bsumsA; n = N_NODES; b = blockIdx.x; }
    else                     { cnt = s_cnt;   ptr = s_ptr;   bsums = bsumsB; n = USER_NUM; b = blockIdx.x - ADJ_NB; }
    int i = b * SB + threadIdx.x;
    int v = (i < n) ? cnt[i] : 0;
    sh[threadIdx.x] = v;
    __syncthreads();
    for (int off = 1; off < SB; off <<= 1) {
        int t = (threadIdx.x >= off) ? sh[threadIdx.x - off] : 0;
        __syncthreads();
        sh[threadIdx.x] += t;
        __syncthreads();
    }
    if (i < n) ptr[i] = sh[threadIdx.x] - v;
    if (threadIdx.x == SB - 1) bsums[b] = sh[SB - 1];
}

__global__ void scan2_kernel(int* __restrict__ bsumsA, int* __restrict__ bsumsB) {
    __shared__ int sh[SB];
    int* bs = (blockIdx.x == 0) ? bsumsA : bsumsB;
    int nb  = (blockIdx.x == 0) ? ADJ_NB : S_NB;
    int v = (threadIdx.x < nb) ? bs[threadIdx.x] : 0;
    sh[threadIdx.x] = v;
    __syncthreads();
    for (int off = 1; off < SB; off <<= 1) {
        int t = (threadIdx.x >= off) ? sh[threadIdx.x - off] : 0;
        __syncthreads();
        sh[threadIdx.x] += t;
        __syncthreads();
    }
    if (threadIdx.x < nb) bs[threadIdx.x] = sh[threadIdx.x] - v;
}

// add block offsets, seed working offsets, terminate rowptrs, re-zero cnt arrays
__global__ void scan3_kernel(int* __restrict__ adj_ptr, int* __restrict__ adj_w,
                             int* __restrict__ s_ptr, int* __restrict__ s_w,
                             const int* __restrict__ bsumsA, const int* __restrict__ bsumsB,
                             int* __restrict__ adj_cnt, int* __restrict__ s_cnt) {
    int i = blockIdx.x * blockDim.x + threadIdx.x;
    if (i < N_NODES) {
        int p = adj_ptr[i] + bsumsA[i / SB];
        adj_ptr[i] = p; adj_w[i] = p; adj_cnt[i] = 0;
        if (i == 0) adj_ptr[N_NODES] = ADJ_NNZ;
    } else if (i < N_NODES + USER_NUM) {
        int j = i - N_NODES;
        int p = s_ptr[j] + bsumsB[j / SB];
        s_ptr[j] = p; s_w[j] = p; s_cnt[j] = 0;
        if (j == 0) s_ptr[USER_NUM] = S_NNZ;
    }
}

// scatter both edge lists into packed (col,val) CSR payload
__global__ void scatter_kernel(const int* __restrict__ adj_rows, const int* __restrict__ adj_cols,
                               const float* __restrict__ adj_vals, int* __restrict__ adj_w,
                               uint2* __restrict__ adj_cv,
                               const int* __restrict__ s_rows, const int* __restrict__ s_cols,
                               const float* __restrict__ s_vals, int* __restrict__ s_w,
                               uint2* __restrict__ s_cv) {
    int i = blockIdx.x * blockDim.x + threadIdx.x;
    if (i < ADJ_NNZ) {
        int p = atomicAdd(adj_w + __ldcs(adj_rows + i), 1);
        adj_cv[p] = make_uint2((unsigned)__ldcs(adj_cols + i), __float_as_uint(__ldcs(adj_vals + i)));
    } else if (i < ADJ_NNZ + S_NNZ) {
        int j = i - ADJ_NNZ;
        int p = atomicAdd(s_w + __ldcs(s_rows + j), 1);
        s_cv[p] = make_uint2((unsigned)__ldcs(s_cols + j), __float_as_uint(__ldcs(s_vals + j)));
    }
}

// ---------------- warp-per-row gather core (direct cv loads, MLP-4) ----------------
template <bool DUAL>
__device__ __forceinline__ float2 row_accum(const uint2* __restrict__ cv, int e, int end,
                                            int lane, const __half* __restrict__ ego,
                                            const __half* __restrict__ h, float2 a) {
    for (; e + 3 < end; e += 4) {
        uint2 cv0 = __ldg(cv + e),     cv1 = __ldg(cv + e + 1);
        uint2 cv2 = __ldg(cv + e + 2), cv3 = __ldg(cv + e + 3);
        const __half* b0 = (DUAL && cv0.x < USER_NUM) ? h : ego;
        const __half* b1 = (DUAL && cv1.x < USER_NUM) ? h : ego;
        const __half* b2 = (DUAL && cv2.x < USER_NUM) ? h : ego;
        const __half* b3 = (DUAL && cv3.x < USER_NUM) ? h : ego;
        float2 x0 = __half22float2(__ldg((const __half2*)(b0 + (size_t)cv0.x * EMB) + lane));
        float2 x1 = __half22float2(__ldg((const __half2*)(b1 + (size_t)cv1.x * EMB) + lane));
        float2 x2 = __half22float2(__ldg((const __half2*)(b2 + (size_t)cv2.x * EMB) + lane));
        float2 x3 = __half22float2(__ldg((const __half2*)(b3 + (size_t)cv3.x * EMB) + lane));
        float w0 = __uint_as_float(cv0.y), w1 = __uint_as_float(cv1.y);
        float w2 = __uint_as_float(cv2.y), w3 = __uint_as_float(cv3.y);
        a.x = fmaf(w0, x0.x, fmaf(w1, x1.x, fmaf(w2, x2.x, fmaf(w3, x3.x, a.x))));
        a.y = fmaf(w0, x0.y, fmaf(w1, x1.y, fmaf(w2, x2.y, fmaf(w3, x3.y, a.y))));
    }
    for (; e < end; e++) {
        uint2 cv0 = __ldg(cv + e);
        float w0 = __uint_as_float(cv0.y);
        const __half* b0 = (DUAL && cv0.x < USER_NUM) ? h : ego;
        float2 x0 = __half22float2(__ldg((const __half2*)(b0 + (size_t)cv0.x * EMB) + lane));
        a.x = fmaf(w0, x0.x, a.x);
        a.y = fmaf(w0, x0.y, a.y);
    }
    return a;
}

// h[r] = ego[r] + sum val*ego[col]   (users)
__global__ void s_spmm_kernel(const int* __restrict__ ptr, const uint2* __restrict__ cv,
                              const __half* __restrict__ ego, __half* __restrict__ h) {
    int row = blockIdx.x * (blockDim.x >> 5) + (threadIdx.x >> 5);
    int lane = threadIdx.x & 31;
    if (row >= USER_NUM) return;
    int e0 = __ldg(ptr + row), end = __ldg(ptr + row + 1);
    float2 a = __half22float2(((const __half2*)(ego + (size_t)row * EMB))[lane]); // self term
    a = row_accum<false>(cv, e0, end, lane, ego, ego, a);
    ((__half2*)(h + (size_t)row * EMB))[lane] = __floats2half2_rn(a.x, a.y);
}

// a = sum val*sel(col); sel = h (users) / ego (items)
// last==0: nxt[r] = half(a)
// last==1: out[r] = (input_row + ego1[r] + ego2[r] + a) * 0.25  (ego param IS ego2 on last)
__global__ void adj_spmm_kernel(const int* __restrict__ ptr, const uint2* __restrict__ cv,
                                const __half* __restrict__ ego, const __half* __restrict__ h,
                                __half* __restrict__ nxt,
                                const float* __restrict__ ue, const float* __restrict__ ie,
                                const __half* __restrict__ ego1,
                                float* __restrict__ out, int last) {
    int row = blockIdx.x * (blockDim.x >> 5) + (threadIdx.x >> 5);
    int lane = threadIdx.x & 31;
    if (row >= N_NODES) return;
    int e0 = __ldg(ptr + row), end = __ldg(ptr + row + 1);
    float2 a = row_accum<true>(cv, e0, end, lane, ego, h, make_float2(0.f, 0.f));
    if (last) {
        const float2* in0 = (row < USER_NUM)
            ? (const float2*)ue + (size_t)row * (EMB / 2)
            : (const float2*)ie + (size_t)(row - USER_NUM) * (EMB / 2);
        float2 v0 = __ldg(in0 + lane);                                            // ego0 (exact)
        float2 v1 = __half22float2(__ldg((const __half2*)(ego1 + (size_t)row * EMB) + lane));
        float2 v2 = __half22float2(__ldg((const __half2*)(ego  + (size_t)row * EMB) + lane));
        ((float2*)(out + (size_t)row * EMB))[lane] =
            make_float2((v0.x + v1.x + v2.x + a.x) * 0.25f,
                        (v0.y + v1.y + v2.y + a.y) * 0.25f);
    } else {
        ((__half2*)(nxt + (size_t)row * EMB))[lane] = __floats2half2_rn(a.x, a.y);
    }
}

extern "C" void kernel_launch(void* const* d_in, const int* in_sizes, int n_in,
                              void* d_out, int out_size) {
    const float* ue       = (const float*)d_in[0];
    const float* ie       = (const float*)d_in[1];
    const int*   adj_rows = (const int*)d_in[2];
    const int*   adj_cols = (const int*)d_in[3];
    const float* adj_vals = (const float*)d_in[4];
    const int*   s_rows   = (const int*)d_in[5];
    const int*   s_cols   = (const int*)d_in[6];
    const float* s_vals   = (const float*)d_in[7];

    __half *egoA, *egoB, *egoC, *h;
    int *adj_cnt, *adj_ptr, *adj_w, *s_cnt, *s_ptr, *s_w, *bsumsA, *bsumsB;
    uint2 *adj_cv, *s_cv;
    cudaGetSymbolAddress((void**)&egoA,    g_egoA);
    cudaGetSymbolAddress((void**)&egoB,    g_egoB);
    cudaGetSymbolAddress((void**)&egoC,    g_egoC);
    cudaGetSymbolAddress((void**)&h,       g_h);
    cudaGetSymbolAddress((void**)&adj_cnt, g_adj_cnt);
    cudaGetSymbolAddress((void**)&adj_ptr, g_adj_ptr);
    cudaGetSymbolAddress((void**)&adj_w,   g_adj_w);
    cudaGetSymbolAddress((void**)&adj_cv,  g_adj_cv);
    cudaGetSymbolAddress((void**)&s_cnt,   g_s_cnt);
    cudaGetSymbolAddress((void**)&s_ptr,   g_s_ptr);
    cudaGetSymbolAddress((void**)&s_w,     g_s_w);
    cudaGetSymbolAddress((void**)&s_cv,    g_s_cv);
    cudaGetSymbolAddress((void**)&bsumsA,  g_bsumsA);
    cudaGetSymbolAddress((void**)&bsumsB,  g_bsumsB);

    const int TPB = 256;

    // ---- build CSR for both matrices + init ego0 (5 kernels) ----
    {
        int tot = ADJ_NNZ + S_NNZ + TOT / 2;
        hist_init_kernel<<<(tot + TPB - 1) / TPB, TPB>>>(adj_rows, s_rows, adj_cnt, s_cnt,
                                                         ue, ie, egoA);
    }
    scan1_kernel<<<ADJ_NB + S_NB, SB>>>(adj_cnt, adj_ptr, s_cnt, s_ptr, bsumsA, bsumsB);
    scan2_kernel<<<2, SB>>>(bsumsA, bsumsB);
    {
        int tot = N_NODES + USER_NUM;
        scan3_kernel<<<(tot + TPB - 1) / TPB, TPB>>>(adj_ptr, adj_w, s_ptr, s_w,
                                                     bsumsA, bsumsB, adj_cnt, s_cnt);
    }
    {
        int tot = ADJ_NNZ + S_NNZ;
        scatter_kernel<<<(tot + TPB - 1) / TPB, TPB>>>(adj_rows, adj_cols, adj_vals, adj_w, adj_cv,
                                                       s_rows, s_cols, s_vals, s_w, s_cv);
    }

    // ---- 3 layers (6 kernels); ego0=egoA, ego1=egoB, ego2=egoC ----
    const int wpb = TPB / 32;
    const int s_blocks   = (USER_NUM + wpb - 1) / wpb;
    const int adj_blocks = (N_NODES + wpb - 1) / wpb;

    // layer 0: read egoA -> write egoB
    s_spmm_kernel<<<s_blocks, TPB>>>(s_ptr, s_cv, egoA, h);
    adj_spmm_kernel<<<adj_blocks, TPB>>>(adj_ptr, adj_cv, egoA, h, egoB,
                                         ue, ie, egoB, (float*)d_out, 0);
    // layer 1: read egoB -> write egoC
    s_spmm_kernel<<<s_blocks, TPB>>>(s_ptr, s_cv, egoB, h);
    adj_spmm_kernel<<<adj_blocks, TPB>>>(adj_ptr, adj_cv, egoB, h, egoC,
                                         ue, ie, egoB, (float*)d_out, 0);
    // layer 2: read egoC -> fused final: out = (input + egoB + egoC + a) / 4
    s_spmm_kernel<<<s_blocks, TPB>>>(s_ptr, s_cv, egoC, h);
    adj_spmm_kernel<<<adj_blocks, TPB>>>(adj_ptr, adj_cv, egoC, h, /*nxt*/egoA,
                                         ue, ie, egoB, (float*)d_out, 1);
}

// round 10
// speedup vs baseline: 1.7005x; 1.0775x over previous
#include <cuda_runtime.h>
#include <cuda_fp16.h>

#define USER_NUM 50000
#define N_NODES  100000
#define EMB      64
#define ROWB     128    // bytes per fp16 row
#define ADJ_NNZ  1600000
#define S_NNZ    800000
#define TOT      (N_NODES * EMB)
#define SB 512
#define ADJ_NB ((N_NODES + SB - 1) / SB)    // 196
#define S_NB   ((USER_NUM + SB - 1) / SB)   // 98

// ---------------- scratch (device globals; zero-initialized at load) ----------------
__device__ __half g_egoA[TOT];              // ego0 (fp16 copy of inputs)
__device__ __half g_egoB[TOT];              // ego1
__device__ __half g_egoC[TOT];              // ego2
__device__ __half g_hFull[TOT];             // [u' ; v] gather source for ADJ

__device__ int   g_adj_cnt[N_NODES];        // invariant: zero at kernel_launch entry
__device__ int   g_adj_ptr[N_NODES + 1];
__device__ int   g_adj_w[N_NODES];
__device__ uint2 g_adj_cv[ADJ_NNZ];         // (col*128, val bits)

__device__ int   g_s_cnt[USER_NUM];         // invariant: zero at kernel_launch entry
__device__ int   g_s_ptr[USER_NUM + 1];
__device__ int   g_s_w[USER_NUM];
__device__ uint2 g_s_cv[S_NNZ];             // (col*128, val bits)

__device__ int   g_bsumsA[SB];
__device__ int   g_bsumsB[SB];

// ---------------- fused: hist(adj) + hist(s) + init(ego0 fp16) ----------------
__global__ void hist_init_kernel(const int* __restrict__ adj_rows, const int* __restrict__ s_rows,
                                 int* __restrict__ adj_cnt, int* __restrict__ s_cnt,
                                 const float* __restrict__ ue, const float* __restrict__ ie,
                                 __half* __restrict__ ego) {
    int i = blockIdx.x * blockDim.x + threadIdx.x;
    if (i < ADJ_NNZ) {
        atomicAdd(adj_cnt + __ldcs(adj_rows + i), 1);
    } else if (i < ADJ_NNZ + S_NNZ) {
        atomicAdd(s_cnt + __ldcs(s_rows + (i - ADJ_NNZ)), 1);
    } else if (i < ADJ_NNZ + S_NNZ + TOT / 2) {
        int j = i - (ADJ_NNZ + S_NNZ);             // half2/float2 index
        const float2* src = (j < USER_NUM * EMB / 2) ? (const float2*)ue
                                                     : (const float2*)ie - USER_NUM * EMB / 2;
        float2 v = src[j];
        ((__half2*)ego)[j] = __floats2half2_rn(v.x, v.y);
    }
}

// per-block exclusive scans of both count arrays
__global__ void scan1_kernel(const int* __restrict__ adj_cnt, int* __restrict__ adj_ptr,
                             const int* __restrict__ s_cnt, int* __restrict__ s_ptr,
                             int* __restrict__ bsumsA, int* __restrict__ bsumsB) {
    __shared__ int sh[SB];
    const int* cnt; int* ptr; int* bsums; int n; int b;
    if (blockIdx.x < ADJ_NB) { cnt = adj_cnt; ptr = adj_ptr; bsums = bsumsA; n = N_NODES; b = blockIdx.x; }
    else                     { cnt = s_cnt;   ptr = s_ptr;   bsums = bsumsB; n = USER_NUM; b = blockIdx.x - ADJ_NB; }
    int i = b * SB + threadIdx.x;
    int v = (i < n) ? cnt[i] : 0;
    sh[threadIdx.x] = v;
    __syncthreads();
    for (int off = 1; off < SB; off <<= 1) {
        int t = (threadIdx.x >= off) ? sh[threadIdx.x - off] : 0;
        __syncthreads();
        sh[threadIdx.x] += t;
        __syncthreads();
    }
    if (i < n) ptr[i] = sh[threadIdx.x] - v;
    if (threadIdx.x == SB - 1) bsums[b] = sh[SB - 1];
}

__global__ void scan2_kernel(int* __restrict__ bsumsA, int* __restrict__ bsumsB) {
    __shared__ int sh[SB];
    int* bs = (blockIdx.x == 0) ? bsumsA : bsumsB;
    int nb  = (blockIdx.x == 0) ? ADJ_NB : S_NB;
    int v = (threadIdx.x < nb) ? bs[threadIdx.x] : 0;
    sh[threadIdx.x] = v;
    __syncthreads();
    for (int off = 1; off < SB; off <<= 1) {
        int t = (threadIdx.x >= off) ? sh[threadIdx.x - off] : 0;
        __syncthreads();
        sh[threadIdx.x] += t;
        __syncthreads();
    }
    if (threadIdx.x < nb) bs[threadIdx.x] = sh[threadIdx.x] - v;
}

// add block offsets, seed working offsets, terminate rowptrs, re-zero cnt arrays
__global__ void scan3_kernel(int* __restrict__ adj_ptr, int* __restrict__ adj_w,
                             int* __restrict__ s_ptr, int* __restrict__ s_w,
                             const int* __restrict__ bsumsA, const int* __restrict__ bsumsB,
                             int* __restrict__ adj_cnt, int* __restrict__ s_cnt) {
    int i = blockIdx.x * blockDim.x + threadIdx.x;
    if (i < N_NODES) {
        int p = adj_ptr[i] + bsumsA[i / SB];
        adj_ptr[i] = p; adj_w[i] = p; adj_cnt[i] = 0;
        if (i == 0) adj_ptr[N_NODES] = ADJ_NNZ;
    } else if (i < N_NODES + USER_NUM) {
        int j = i - N_NODES;
        int p = s_ptr[j] + bsumsB[j / SB];
        s_ptr[j] = p; s_w[j] = p; s_cnt[j] = 0;
        if (j == 0) s_ptr[USER_NUM] = S_NNZ;
    }
}

// scatter both edge lists into packed (col*128, val) CSR payload
__global__ void scatter_kernel(const int* __restrict__ adj_rows, const int* __restrict__ adj_cols,
                               const float* __restrict__ adj_vals, int* __restrict__ adj_w,
                               uint2* __restrict__ adj_cv,
                               const int* __restrict__ s_rows, const int* __restrict__ s_cols,
                               const float* __restrict__ s_vals, int* __restrict__ s_w,
                               uint2* __restrict__ s_cv) {
    int i = blockIdx.x * blockDim.x + threadIdx.x;
    if (i < ADJ_NNZ) {
        int p = atomicAdd(adj_w + __ldcs(adj_rows + i), 1);
        adj_cv[p] = make_uint2((unsigned)__ldcs(adj_cols + i) * ROWB,
                               __float_as_uint(__ldcs(adj_vals + i)));
    } else if (i < ADJ_NNZ + S_NNZ) {
        int j = i - ADJ_NNZ;
        int p = atomicAdd(s_w + __ldcs(s_rows + j), 1);
        s_cv[p] = make_uint2((unsigned)__ldcs(s_cols + j) * ROWB,
                             __float_as_uint(__ldcs(s_vals + j)));
    }
}

// ---------------- warp-per-row gather core (single base, byte-offset cols, MLP-4) ----------------
__device__ __forceinline__ float2 row_accum(const uint2* __restrict__ cv, int e, int end,
                                            int lane, const char* __restrict__ base, float2 a) {
    const int lb = lane * 4;   // byte offset of this lane's half2 within a row
    for (; e + 3 < end; e += 4) {
        uint2 c0 = __ldg(cv + e),     c1 = __ldg(cv + e + 1);
        uint2 c2 = __ldg(cv + e + 2), c3 = __ldg(cv + e + 3);
        float2 x0 = __half22float2(__ldg((const __half2*)(base + c0.x + lb)));
        float2 x1 = __half22float2(__ldg((const __half2*)(base + c1.x + lb)));
        float2 x2 = __half22float2(__ldg((const __half2*)(base + c2.x + lb)));
        float2 x3 = __half22float2(__ldg((const __half2*)(base + c3.x + lb)));
        float w0 = __uint_as_float(c0.y), w1 = __uint_as_float(c1.y);
        float w2 = __uint_as_float(c2.y), w3 = __uint_as_float(c3.y);
        a.x = fmaf(w0, x0.x, fmaf(w1, x1.x, fmaf(w2, x2.x, fmaf(w3, x3.x, a.x))));
        a.y = fmaf(w0, x0.y, fmaf(w1, x1.y, fmaf(w2, x2.y, fmaf(w3, x3.y, a.y))));
    }
    for (; e < end; e++) {
        uint2 c0 = __ldg(cv + e);
        float w0 = __uint_as_float(c0.y);
        float2 x0 = __half22float2(__ldg((const __half2*)(base + c0.x + lb)));
        a.x = fmaf(w0, x0.x, a.x);
        a.y = fmaf(w0, x0.y, a.y);
    }
    return a;
}

// rows < USER_NUM: hFull[r] = ego[r] + sum val*ego[col]
// rows >= USER_NUM: hFull[r] = ego[r]   (item passthrough copy)
__global__ void s_spmm_kernel(const int* __restrict__ ptr, const uint2* __restrict__ cv,
                              const __half* __restrict__ ego, __half* __restrict__ hFull) {
    int row = blockIdx.x * (blockDim.x >> 5) + (threadIdx.x >> 5);
    int lane = threadIdx.x & 31;
    if (row >= N_NODES) return;
    __half2 self = ((const __half2*)(ego + (size_t)row * EMB))[lane];
    if (row < USER_NUM) {
        int e0 = __ldg(ptr + row), end = __ldg(ptr + row + 1);
        float2 a = __half22float2(self);
        a = row_accum(cv, e0, end, lane, (const char*)ego, a);
        ((__half2*)(hFull + (size_t)row * EMB))[lane] = __floats2half2_rn(a.x, a.y);
    } else {
        ((__half2*)(hFull + (size_t)row * EMB))[lane] = self;
    }
}

// a = sum val * hFull[col]
// last==0: nxt[r] = half(a)
// last==1: out[r] = (input_row + ego1[r] + ego2[r] + a) * 0.25  (ego param IS ego2 on last)
__global__ void adj_spmm_kernel(const int* __restrict__ ptr, const uint2* __restrict__ cv,
                                const __half* __restrict__ hFull, const __half* __restrict__ ego,
                                __half* __restrict__ nxt,
                                const float* __restrict__ ue, const float* __restrict__ ie,
                                const __half* __restrict__ ego1,
                                float* __restrict__ out, int last) {
    int row = blockIdx.x * (blockDim.x >> 5) + (threadIdx.x >> 5);
    int lane = threadIdx.x & 31;
    if (row >= N_NODES) return;
    int e0 = __ldg(ptr + row), end = __ldg(ptr + row + 1);
    float2 a = row_accum(cv, e0, end, lane, (const char*)hFull, make_float2(0.f, 0.f));
    if (last) {
        const float2* in0 = (row < USER_NUM)
            ? (const float2*)ue + (size_t)row * (EMB / 2)
            : (const float2*)ie + (size_t)(row - USER_NUM) * (EMB / 2);
        float2 v0 = __ldg(in0 + lane);                                            // ego0 (exact)
        float2 v1 = __half22float2(__ldg((const __half2*)(ego1 + (size_t)row * EMB) + lane));
        float2 v2 = __half22float2(__ldg((const __half2*)(ego  + (size_t)row * EMB) + lane));
        ((float2*)(out + (size_t)row * EMB))[lane] =
            make_float2((v0.x + v1.x + v2.x + a.x) * 0.25f,
                        (v0.y + v1.y + v2.y + a.y) * 0.25f);
    } else {
        ((__half2*)(nxt + (size_t)row * EMB))[lane] = __floats2half2_rn(a.x, a.y);
    }
}

extern "C" void kernel_launch(void* const* d_in, const int* in_sizes, int n_in,
                              void* d_out, int out_size) {
    const float* ue       = (const float*)d_in[0];
    const float* ie       = (const float*)d_in[1];
    const int*   adj_rows = (const int*)d_in[2];
    const int*   adj_cols = (const int*)d_in[3];
    const float* adj_vals = (const float*)d_in[4];
    const int*   s_rows   = (const int*)d_in[5];
    const int*   s_cols   = (const int*)d_in[6];
    const float* s_vals   = (const float*)d_in[7];

    __half *egoA, *egoB, *egoC, *hFull;
    int *adj_cnt, *adj_ptr, *adj_w, *s_cnt, *s_ptr, *s_w, *bsumsA, *bsumsB;
    uint2 *adj_cv, *s_cv;
    cudaGetSymbolAddress((void**)&egoA,    g_egoA);
    cudaGetSymbolAddress((void**)&egoB,    g_egoB);
    cudaGetSymbolAddress((void**)&egoC,    g_egoC);
    cudaGetSymbolAddress((void**)&hFull,   g_hFull);
    cudaGetSymbolAddress((void**)&adj_cnt, g_adj_cnt);
    cudaGetSymbolAddress((void**)&adj_ptr, g_adj_ptr);
    cudaGetSymbolAddress((void**)&adj_w,   g_adj_w);
    cudaGetSymbolAddress((void**)&adj_cv,  g_adj_cv);
    cudaGetSymbolAddress((void**)&s_cnt,   g_s_cnt);
    cudaGetSymbolAddress((void**)&s_ptr,   g_s_ptr);
    cudaGetSymbolAddress((void**)&s_w,     g_s_w);
    cudaGetSymbolAddress((void**)&s_cv,    g_s_cv);
    cudaGetSymbolAddress((void**)&bsumsA,  g_bsumsA);
    cudaGetSymbolAddress((void**)&bsumsB,  g_bsumsB);

    const int TPB = 256;

    // ---- build CSR for both matrices + init ego0 (5 kernels) ----
    {
        int tot = ADJ_NNZ + S_NNZ + TOT / 2;
        hist_init_kernel<<<(tot + TPB - 1) / TPB, TPB>>>(adj_rows, s_rows, adj_cnt, s_cnt,
                                                         ue, ie, egoA);
    }
    scan1_kernel<<<ADJ_NB + S_NB, SB>>>(adj_cnt, adj_ptr, s_cnt, s_ptr, bsumsA, bsumsB);
    scan2_kernel<<<2, SB>>>(bsumsA, bsumsB);
    {
        int tot = N_NODES + USER_NUM;
        scan3_kernel<<<(tot + TPB - 1) / TPB, TPB>>>(adj_ptr, adj_w, s_ptr, s_w,
                                                     bsumsA, bsumsB, adj_cnt, s_cnt);
    }
    {
        int tot = ADJ_NNZ + S_NNZ;
        scatter_kernel<<<(tot + TPB - 1) / TPB, TPB>>>(adj_rows, adj_cols, adj_vals, adj_w, adj_cv,
                                                       s_rows, s_cols, s_vals, s_w, s_cv);
    }

    // ---- 3 layers (6 kernels); ego0=egoA, ego1=egoB, ego2=egoC ----
    const int wpb = TPB / 32;
    const int all_blocks = (N_NODES + wpb - 1) / wpb;

    // layer 0: read egoA -> write egoB
    s_spmm_kernel<<<all_blocks, TPB>>>(s_ptr, s_cv, egoA, hFull);
    adj_spmm_kernel<<<all_blocks, TPB>>>(adj_ptr, adj_cv, hFull, egoA, egoB,
                                         ue, ie, egoB, (float*)d_out, 0);
    // layer 1: read egoB -> write egoC
    s_spmm_kernel<<<all_blocks, TPB>>>(s_ptr, s_cv, egoB, hFull);
    adj_spmm_kernel<<<all_blocks, TPB>>>(adj_ptr, adj_cv, hFull, egoB, egoC,
                                         ue, ie, egoB, (float*)d_out, 0);
    // layer 2: read egoC -> fused final: out = (input + egoB + egoC + a) / 4
    s_spmm_kernel<<<all_blocks, TPB>>>(s_ptr, s_cv, egoC, hFull);
    adj_spmm_kernel<<<all_blocks, TPB>>>(adj_ptr, adj_cv, hFull, egoC, /*nxt*/egoA,
                                         ue, ie, egoB, (float*)d_out, 1);
}